// round 10
// baseline (speedup 1.0000x reference)
#include <cuda_runtime.h>
#include <cuda_bf16.h>
#include <cstdint>

#define BATCH   2
#define SEQ     2048
#define EMB     1024
#define HEADS   16
#define HDIM    64
#define MTOT    (BATCH*SEQ)        // 4096
#define BH      (BATCH*HEADS)      // 32
#define SCALE   0.125f

// ---------------- scratch (device globals; cudaMalloc forbidden) -----------
__device__ __nv_bfloat16 g_x_hi[MTOT*EMB],   g_x_lo[MTOT*EMB];
__device__ __nv_bfloat16 g_wq_hi[3*EMB*EMB], g_wq_lo[3*EMB*EMB];
__device__ __nv_bfloat16 g_wo_hi[EMB*EMB],   g_wo_lo[EMB*EMB];
__device__ __nv_bfloat16 g_cx_hi[MTOT*EMB],  g_cx_lo[MTOT*EMB];
__device__ __nv_bfloat16 g_q_hi[BH*SEQ*HDIM],  g_q_lo[BH*SEQ*HDIM];   // [bh][n][d], pre-scaled
__device__ __nv_bfloat16 g_k_hi[BH*SEQ*HDIM],  g_k_lo[BH*SEQ*HDIM];   // [bh][n][d]
__device__ __nv_bfloat16 g_vT_hi[BH*HDIM*SEQ], g_vT_lo[BH*HDIM*SEQ];  // [bh][d][n]

// ---------------- helpers --------------------------------------------------
__device__ __forceinline__ uint32_t smem_u32(const void* p) {
    uint32_t a;
    asm("{ .reg .u64 t; cvta.to.shared.u64 t, %1; cvt.u32.u64 %0, t; }"
        : "=r"(a) : "l"(p));
    return a;
}
#define SW(off) ((uint32_t)(off) ^ ((((uint32_t)(off)) >> 3) & 0x70))

__device__ __forceinline__ void ldsm_x4(uint32_t& r0, uint32_t& r1,
                                        uint32_t& r2, uint32_t& r3, uint32_t addr) {
    asm volatile("ldmatrix.sync.aligned.m8n8.x4.shared.b16 {%0,%1,%2,%3}, [%4];"
                 : "=r"(r0), "=r"(r1), "=r"(r2), "=r"(r3) : "r"(addr));
}
__device__ __forceinline__ void mma16816(float c[4],
                                         uint32_t a0, uint32_t a1, uint32_t a2, uint32_t a3,
                                         uint32_t b0, uint32_t b1) {
    asm volatile("mma.sync.aligned.m16n8k16.row.col.f32.bf16.bf16.f32 "
                 "{%0,%1,%2,%3}, {%4,%5,%6,%7}, {%8,%9}, {%0,%1,%2,%3};"
                 : "+f"(c[0]), "+f"(c[1]), "+f"(c[2]), "+f"(c[3])
                 : "r"(a0), "r"(a1), "r"(a2), "r"(a3), "r"(b0), "r"(b1));
}
__device__ __forceinline__ void cp16(uint32_t dst, const void* src) {
    asm volatile("cp.async.cg.shared.global [%0], [%1], 16;" :: "r"(dst), "l"(src));
}
#define CP_COMMIT()  asm volatile("cp.async.commit_group;" ::: "memory")
#define CP_WAIT0()   asm volatile("cp.async.wait_group 0;" ::: "memory")
#define CP_WAIT1()   asm volatile("cp.async.wait_group 1;" ::: "memory")
#define CP_WAIT2()   asm volatile("cp.async.wait_group 2;" ::: "memory")

__device__ __forceinline__ void split_pack(float v0, float v1, uint32_t& hi, uint32_t& lo) {
    __nv_bfloat16 h0 = __float2bfloat16(v0), h1 = __float2bfloat16(v1);
    __nv_bfloat16 l0 = __float2bfloat16(v0 - __bfloat162float(h0));
    __nv_bfloat16 l1 = __float2bfloat16(v1 - __bfloat162float(h1));
    hi = (uint32_t)__bfloat16_as_ushort(h0) | ((uint32_t)__bfloat16_as_ushort(h1) << 16);
    lo = (uint32_t)__bfloat16_as_ushort(l0) | ((uint32_t)__bfloat16_as_ushort(l1) << 16);
}

// ---------------------------------------------------------------------------
// Split fp32 -> bf16 hi/lo (which: 0=x, 1=w_qkv, 2=w_out)
// ---------------------------------------------------------------------------
__global__ __launch_bounds__(256) void split_kernel(
    const float* __restrict__ in, int n4, int which)
{
    int i = blockIdx.x * 256 + threadIdx.x;
    if (i >= n4) return;
    __nv_bfloat16 *hi, *lo;
    if (which == 0)      { hi = g_x_hi;  lo = g_x_lo;  }
    else if (which == 1) { hi = g_wq_hi; lo = g_wq_lo; }
    else                 { hi = g_wo_hi; lo = g_wo_lo; }
    float4 v = ((const float4*)in)[i];
    uint32_t h01, l01, h23, l23;
    split_pack(v.x, v.y, h01, l01);
    split_pack(v.z, v.w, h23, l23);
    ((uint2*)hi)[i] = make_uint2(h01, h23);
    ((uint2*)lo)[i] = make_uint2(l01, l23);
}

// ---------------------------------------------------------------------------
// HMMA split-bf16 GEMM, cp.async 3-stage pipeline, pass-reordered MMAs
// (same-accumulator revisit distance = 16 MMAs, past HMMA latency).
// ---------------------------------------------------------------------------
#define GSTAGE    65536
#define GEMM_SMEM (3*GSTAGE)

__global__ __launch_bounds__(256) void tc_gemm(
    const float* __restrict__ bias, float* __restrict__ out, int mode)
{
    extern __shared__ char sb[];
    const uint32_t sbu = smem_u32(sb);
    const int tid = threadIdx.x;
    const int wid = tid >> 5, lane = tid & 31;
    const int wm = wid >> 2, wn = wid & 3;
    const int m0 = blockIdx.y * 128, n0 = blockIdx.x * 128;

    const char *Ahg, *Alg, *Bhg, *Blg;
    if (mode == 0) {
        Ahg = (const char*)(g_x_hi  + (size_t)m0 * EMB);
        Alg = (const char*)(g_x_lo  + (size_t)m0 * EMB);
        Bhg = (const char*)(g_wq_hi + (size_t)n0 * EMB);
        Blg = (const char*)(g_wq_lo + (size_t)n0 * EMB);
    } else {
        Ahg = (const char*)(g_cx_hi + (size_t)m0 * EMB);
        Alg = (const char*)(g_cx_lo + (size_t)m0 * EMB);
        Bhg = (const char*)(g_wo_hi + (size_t)n0 * EMB);
        Blg = (const char*)(g_wo_lo + (size_t)n0 * EMB);
    }

    float acc[4][4][4];
#pragma unroll
    for (int i = 0; i < 4; i++)
#pragma unroll
        for (int j = 0; j < 4; j++)
#pragma unroll
            for (int e = 0; e < 4; e++) acc[i][j][e] = 0.f;

    const int a_r  = (lane & 7) + ((lane >> 3) & 1) * 8;
    const int a_kb = (lane >> 4) * 16;
    const int b_r  = (lane & 7) + (lane >> 4) * 8;
    const int b_kb = ((lane >> 3) & 1) * 16;

    auto load_stage = [&](int c, int s) {
        const uint32_t base = sbu + s * GSTAGE;
#pragma unroll
        for (int it = 0; it < 4; it++) {
            const int idx = tid + it * 256;
            const int r = idx >> 3, in = (idx & 7) * 16;
            const uint32_t sw = SW(r * 128 + in);
            const size_t g = (size_t)r * 2048 + (size_t)c * 128 + in;
            cp16(base + sw,          Ahg + g);
            cp16(base + 16384 + sw,  Alg + g);
            cp16(base + 32768 + sw,  Bhg + g);
            cp16(base + 49152 + sw,  Blg + g);
        }
    };

    load_stage(0, 0); CP_COMMIT();
    load_stage(1, 1); CP_COMMIT();

    for (int c = 0; c < 16; c++) {
        const int buf = c % 3;
        if (c + 2 < 16) { load_stage(c + 2, (c + 2) % 3); CP_COMMIT(); CP_WAIT2(); }
        else if (c == 14) { CP_WAIT1(); }
        else              { CP_WAIT0(); }
        __syncthreads();

        const uint32_t Ah = sbu + buf * GSTAGE;
        const uint32_t Al = Ah + 16384, Bh = Ah + 32768, Bl = Ah + 49152;
#pragma unroll
        for (int ks = 0; ks < 4; ks++) {
            const int kb = ks * 32;
            uint32_t ah[4][4], al[4][4], bh[2][4], bl[2][4];
#pragma unroll
            for (int mt = 0; mt < 4; mt++) {
                const int row = wm * 64 + mt * 16 + a_r;
                ldsm_x4(ah[mt][0], ah[mt][1], ah[mt][2], ah[mt][3],
                        Ah + SW(row * 128 + kb + a_kb));
                ldsm_x4(al[mt][0], al[mt][1], al[mt][2], al[mt][3],
                        Al + SW(row * 128 + kb + a_kb));
            }
#pragma unroll
            for (int p = 0; p < 2; p++) {
                const int row = wn * 32 + p * 16 + b_r;
                ldsm_x4(bh[p][0], bh[p][1], bh[p][2], bh[p][3],
                        Bh + SW(row * 128 + kb + b_kb));
                ldsm_x4(bl[p][0], bl[p][1], bl[p][2], bl[p][3],
                        Bl + SW(row * 128 + kb + b_kb));
            }
            // pass 1: Ah x Bh  (16 distinct accumulators)
#pragma unroll
            for (int mt = 0; mt < 4; mt++)
#pragma unroll
                for (int p = 0; p < 2; p++) {
                    mma16816(acc[mt][p*2],   ah[mt][0], ah[mt][1], ah[mt][2], ah[mt][3], bh[p][0], bh[p][1]);
                    mma16816(acc[mt][p*2+1], ah[mt][0], ah[mt][1], ah[mt][2], ah[mt][3], bh[p][2], bh[p][3]);
                }
            // pass 2: Al x Bh
#pragma unroll
            for (int mt = 0; mt < 4; mt++)
#pragma unroll
                for (int p = 0; p < 2; p++) {
                    mma16816(acc[mt][p*2],   al[mt][0], al[mt][1], al[mt][2], al[mt][3], bh[p][0], bh[p][1]);
                    mma16816(acc[mt][p*2+1], al[mt][0], al[mt][1], al[mt][2], al[mt][3], bh[p][2], bh[p][3]);
                }
            // pass 3: Ah x Bl
#pragma unroll
            for (int mt = 0; mt < 4; mt++)
#pragma unroll
                for (int p = 0; p < 2; p++) {
                    mma16816(acc[mt][p*2],   ah[mt][0], ah[mt][1], ah[mt][2], ah[mt][3], bl[p][0], bl[p][1]);
                    mma16816(acc[mt][p*2+1], ah[mt][0], ah[mt][1], ah[mt][2], ah[mt][3], bl[p][2], bl[p][3]);
                }
        }
        __syncthreads();
    }

    const int rbase = m0 + wm * 64 + (lane >> 2);
    const int cbase = n0 + wn * 32 + (lane & 3) * 2;
#pragma unroll
    for (int mt = 0; mt < 4; mt++) {
#pragma unroll
        for (int nt = 0; nt < 4; nt++) {
            const int col = cbase + nt * 8;
            const float bx = bias[col], by = bias[col + 1];
#pragma unroll
            for (int half = 0; half < 2; half++) {
                const int row = rbase + mt * 16 + half * 8;
                float v0 = acc[mt][nt][half * 2 + 0] + bx;
                float v1 = acc[mt][nt][half * 2 + 1] + by;
                if (mode == 1) {
                    *(float2*)(out + (size_t)row * EMB + col) = make_float2(v0, v1);
                } else {
                    const int b = row >> 11, n = row & 2047;
                    const int which = col >> 10;
                    const int hd = col & 1023;
                    const int h = hd >> 6, d = hd & 63;
                    const int bhi = (b << 4) + h;
                    if (which == 0) {
                        uint32_t hi, lo;
                        split_pack(v0 * SCALE, v1 * SCALE, hi, lo);
                        const size_t off = ((size_t)bhi * SEQ + n) * HDIM + d;
                        *(uint32_t*)&g_q_hi[off] = hi;
                        *(uint32_t*)&g_q_lo[off] = lo;
                    } else if (which == 1) {
                        uint32_t hi, lo;
                        split_pack(v0, v1, hi, lo);
                        const size_t off = ((size_t)bhi * SEQ + n) * HDIM + d;
                        *(uint32_t*)&g_k_hi[off] = hi;
                        *(uint32_t*)&g_k_lo[off] = lo;
                    } else {
                        __nv_bfloat16 h0 = __float2bfloat16(v0);
                        __nv_bfloat16 h1 = __float2bfloat16(v1);
                        __nv_bfloat16 l0 = __float2bfloat16(v0 - __bfloat162float(h0));
                        __nv_bfloat16 l1 = __float2bfloat16(v1 - __bfloat162float(h1));
                        const size_t o0 = ((size_t)bhi * HDIM + d) * SEQ + n;
                        const size_t o1 = ((size_t)bhi * HDIM + d + 1) * SEQ + n;
                        g_vT_hi[o0] = h0; g_vT_lo[o0] = l0;
                        g_vT_hi[o1] = h1; g_vT_lo[o1] = l1;
                    }
                }
            }
        }
    }
}

// ---------------------------------------------------------------------------
// HMMA flash attention, split bf16, register-resident P, pass-reordered MMAs.
// ---------------------------------------------------------------------------
#define ASTG      65536
#define AS_KV     32768
#define ATTN_SMEM (AS_KV + 3*ASTG)

__global__ __launch_bounds__(256) void attn_kernel()
{
    extern __shared__ char sb[];
    const uint32_t sbu = smem_u32(sb);
    const int tid = threadIdx.x;
    const int wid = tid >> 5, lane = tid & 31;
    const int bh = blockIdx.x;
    const int q0 = blockIdx.y * 128;

    const int a_r  = (lane & 7) + ((lane >> 3) & 1) * 8;
    const int a_kb = (lane >> 4) * 16;
    const int b_r  = (lane & 7) + (lane >> 4) * 8;
    const int b_kb = ((lane >> 3) & 1) * 16;

    // ---- Q tile ----
    {
        const char* qh = (const char*)(g_q_hi + ((size_t)bh * SEQ + q0) * HDIM);
        const char* ql = (const char*)(g_q_lo + ((size_t)bh * SEQ + q0) * HDIM);
#pragma unroll
        for (int it = 0; it < 4; it++) {
            const int idx = tid + it * 256;
            const int r = idx >> 3, in = (idx & 7) * 16;
            const uint32_t sw = SW(r * 128 + in);
            cp16(sbu + sw,         qh + r * 128 + in);
            cp16(sbu + 16384 + sw, ql + r * 128 + in);
        }
    }

    auto load_stage = [&](int kt, int s) {
        const uint32_t base = sbu + AS_KV + s * ASTG;
        const char* kh = (const char*)(g_k_hi + ((size_t)bh * SEQ + kt * 128) * HDIM);
        const char* kl = (const char*)(g_k_lo + ((size_t)bh * SEQ + kt * 128) * HDIM);
#pragma unroll
        for (int it = 0; it < 4; it++) {
            const int idx = tid + it * 256;
            const int r = idx >> 3, in = (idx & 7) * 16;
            const uint32_t sw = SW(r * 128 + in);
            cp16(base + sw,         kh + r * 128 + in);
            cp16(base + 16384 + sw, kl + r * 128 + in);
        }
        const char* vh = (const char*)(g_vT_hi + (size_t)bh * HDIM * SEQ) + (size_t)kt * 256;
        const char* vl = (const char*)(g_vT_lo + (size_t)bh * HDIM * SEQ) + (size_t)kt * 256;
#pragma unroll
        for (int it = 0; it < 4; it++) {
            const int idx = tid + it * 256;
            const int r = idx >> 4;
            const int inner = (idx & 15) * 16;
            const int half = inner >> 7, in128 = inner & 127;
            const uint32_t dst = base + 32768 + half * 8192 + SW(r * 128 + in128);
            cp16(dst,         vh + (size_t)r * 4096 + inner);
            cp16(dst + 16384, vl + (size_t)r * 4096 + inner);
        }
    };

    load_stage(0, 0); CP_COMMIT();
    load_stage(1, 1); CP_COMMIT();

    float o[8][4];
    float mi[2], li[2];
#pragma unroll
    for (int i = 0; i < 8; i++)
#pragma unroll
        for (int e = 0; e < 4; e++) o[i][e] = 0.f;
    mi[0] = mi[1] = -1e30f;
    li[0] = li[1] = 0.f;

    const int arow = wid * 16 + a_r;

    for (int kt = 0; kt < 16; kt++) {
        const int buf = kt % 3;
        if (kt + 2 < 16) { load_stage(kt + 2, (kt + 2) % 3); CP_COMMIT(); CP_WAIT2(); }
        else if (kt == 14) { CP_WAIT1(); }
        else               { CP_WAIT0(); }
        __syncthreads();

        const uint32_t Kh = sbu + AS_KV + buf * ASTG;
        const uint32_t Kl = Kh + 16384;
        const uint32_t Vh = Kh + 32768;
        const uint32_t Vl = Kh + 49152;

        // ---- S = Qh*Kh + Ql*Kh + Qh*Kl (3 passes; acc distance = 16) ----
        float s[16][4];
#pragma unroll
        for (int i = 0; i < 16; i++)
#pragma unroll
            for (int e = 0; e < 4; e++) s[i][e] = 0.f;

#pragma unroll
        for (int ks = 0; ks < 4; ks++) {
            const int kb = ks * 32;
            uint32_t ah0, ah1, ah2, ah3, al0, al1, al2, al3;
            ldsm_x4(ah0, ah1, ah2, ah3, sbu +         SW(arow * 128 + kb + a_kb));
            ldsm_x4(al0, al1, al2, al3, sbu + 16384 + SW(arow * 128 + kb + a_kb));
            // pass 1: Qh x Kh
#pragma unroll
            for (int p = 0; p < 8; p++) {
                uint32_t t0, t1, t2, t3;
                ldsm_x4(t0, t1, t2, t3, Kh + SW((p * 16 + b_r) * 128 + kb + b_kb));
                mma16816(s[p*2],   ah0, ah1, ah2, ah3, t0, t1);
                mma16816(s[p*2+1], ah0, ah1, ah2, ah3, t2, t3);
            }
            // pass 2: Ql x Kh
#pragma unroll
            for (int p = 0; p < 8; p++) {
                uint32_t t0, t1, t2, t3;
                ldsm_x4(t0, t1, t2, t3, Kh + SW((p * 16 + b_r) * 128 + kb + b_kb));
                mma16816(s[p*2],   al0, al1, al2, al3, t0, t1);
                mma16816(s[p*2+1], al0, al1, al2, al3, t2, t3);
            }
            // pass 3: Qh x Kl
#pragma unroll
            for (int p = 0; p < 8; p++) {
                uint32_t t0, t1, t2, t3;
                ldsm_x4(t0, t1, t2, t3, Kl + SW((p * 16 + b_r) * 128 + kb + b_kb));
                mma16816(s[p*2],   ah0, ah1, ah2, ah3, t0, t1);
                mma16816(s[p*2+1], ah0, ah1, ah2, ah3, t2, t3);
            }
        }

        // ---- online softmax (rows lane>>2, lane>>2+8; quad reduce) ----
#pragma unroll
        for (int h = 0; h < 2; h++) {
            float rm = -1e30f;
#pragma unroll
            for (int nt = 0; nt < 16; nt++)
                rm = fmaxf(rm, fmaxf(s[nt][h*2], s[nt][h*2+1]));
            rm = fmaxf(rm, __shfl_xor_sync(0xffffffffu, rm, 1));
            rm = fmaxf(rm, __shfl_xor_sync(0xffffffffu, rm, 2));
            const float m2 = fmaxf(mi[h], rm);
            const float alpha = __expf(mi[h] - m2);
            float rs = 0.f;
#pragma unroll
            for (int nt = 0; nt < 16; nt++) {
                const float p0 = __expf(s[nt][h*2]   - m2);
                const float p1 = __expf(s[nt][h*2+1] - m2);
                s[nt][h*2] = p0; s[nt][h*2+1] = p1;
                rs += p0 + p1;
            }
            rs += __shfl_xor_sync(0xffffffffu, rs, 1);
            rs += __shfl_xor_sync(0xffffffffu, rs, 2);
            li[h] = li[h] * alpha + rs;
            mi[h] = m2;
#pragma unroll
            for (int nt = 0; nt < 8; nt++) {
                o[nt][h*2]   *= alpha;
                o[nt][h*2+1] *= alpha;
            }
        }

        // ---- O += Ph*Vh + Pl*Vh + Ph*Vl (V frags held; acc distance = 8) ----
#pragma unroll
        for (int kc = 0; kc < 8; kc++) {
            const int half = kc >> 2;
            const int koff = (kc & 3) * 32;
            uint32_t ah0, ah1, ah2, ah3, al0, al1, al2, al3;
            split_pack(s[2*kc][0],   s[2*kc][1],   ah0, al0);
            split_pack(s[2*kc][2],   s[2*kc][3],   ah1, al1);
            split_pack(s[2*kc+1][0], s[2*kc+1][1], ah2, al2);
            split_pack(s[2*kc+1][2], s[2*kc+1][3], ah3, al3);
            uint32_t vh[4][4], vl[4][4];
#pragma unroll
            for (int p = 0; p < 4; p++) {
                const uint32_t va = half * 8192 + SW((p * 16 + b_r) * 128 + koff + b_kb);
                ldsm_x4(vh[p][0], vh[p][1], vh[p][2], vh[p][3], Vh + va);
                ldsm_x4(vl[p][0], vl[p][1], vl[p][2], vl[p][3], Vl + va);
            }
#pragma unroll
            for (int p = 0; p < 4; p++) {
                mma16816(o[p*2],   ah0, ah1, ah2, ah3, vh[p][0], vh[p][1]);
                mma16816(o[p*2+1], ah0, ah1, ah2, ah3, vh[p][2], vh[p][3]);
            }
#pragma unroll
            for (int p = 0; p < 4; p++) {
                mma16816(o[p*2],   al0, al1, al2, al3, vh[p][0], vh[p][1]);
                mma16816(o[p*2+1], al0, al1, al2, al3, vh[p][2], vh[p][3]);
            }
#pragma unroll
            for (int p = 0; p < 4; p++) {
                mma16816(o[p*2],   ah0, ah1, ah2, ah3, vl[p][0], vl[p][1]);
                mma16816(o[p*2+1], ah0, ah1, ah2, ah3, vl[p][2], vl[p][3]);
            }
        }
        __syncthreads();
    }

    // ---- epilogue: normalize, split-bf16 ctx in [B,N,H*D] ----
    const int b = bh >> 4, h = bh & 15;
#pragma unroll
    for (int hh = 0; hh < 2; hh++) {
        const float inv = 1.f / li[hh];
        const int row = q0 + wid * 16 + (lane >> 2) + hh * 8;
        const size_t rbase = ((size_t)b * SEQ + row) * EMB + h * HDIM;
#pragma unroll
        for (int nt = 0; nt < 8; nt++) {
            const int col = (lane & 3) * 2 + nt * 8;
            uint32_t hi, lo;
            split_pack(o[nt][hh*2] * inv, o[nt][hh*2+1] * inv, hi, lo);
            *(uint32_t*)&g_cx_hi[rbase + col] = hi;
            *(uint32_t*)&g_cx_lo[rbase + col] = lo;
        }
    }
}

// ---------------------------------------------------------------------------
extern "C" void kernel_launch(void* const* d_in, const int* in_sizes, int n_in,
                              void* d_out, int out_size)
{
    const float* x     = (const float*)d_in[0];
    const float* w_qkv = (const float*)d_in[1];
    const float* b_qkv = (const float*)d_in[2];
    const float* w_out = (const float*)d_in[3];
    const float* b_out = (const float*)d_in[4];
    float* out = (float*)d_out;

    static bool attr_set = false;
    if (!attr_set) {
        cudaFuncSetAttribute(tc_gemm, cudaFuncAttributeMaxDynamicSharedMemorySize, GEMM_SMEM);
        cudaFuncSetAttribute(attn_kernel, cudaFuncAttributeMaxDynamicSharedMemorySize, ATTN_SMEM);
        attr_set = true;
    }

    split_kernel<<<(MTOT*EMB/4 + 255)/256, 256>>>(x, MTOT*EMB/4, 0);
    split_kernel<<<(3*EMB*EMB/4 + 255)/256, 256>>>(w_qkv, 3*EMB*EMB/4, 1);
    split_kernel<<<(EMB*EMB/4 + 255)/256, 256>>>(w_out, EMB*EMB/4, 2);

    tc_gemm<<<dim3(3*EMB/128, MTOT/128), 256, GEMM_SMEM>>>(b_qkv, nullptr, 0);
    attn_kernel<<<dim3(BH, SEQ/128), 256, ATTN_SMEM>>>();
    tc_gemm<<<dim3(EMB/128, MTOT/128), 256, GEMM_SMEM>>>(b_out, out, 1);
}